// round 13
// baseline (speedup 1.0000x reference)
#include <cuda_runtime.h>
#include <cuda_fp16.h>
#include <cstdint>
#include <math.h>

#define N_NODES   8192
#define N_EDGES   131072
#define C_DIM     64
#define NPATHS    15
#define FSTRIDE   576

// ---------------- device scratch ----------------
__device__ float  g_feat [N_NODES * FSTRIDE];    // ping  [n][t][c]
__device__ float  g_feat2[N_NODES * FSTRIDE];    // pong
__device__ float  g_geo  [N_EDGES * 18];         // sorted: sh[9], basis[8], cut
__device__ float  g_Af   [192 * N_EDGES];        // sorted: A tensors, [elem][edge] scalar SoA
__device__ __half g_w    [N_EDGES * 960];        // sorted: edge tp weights (fp16)
__device__ float  g_cg   [NPATHS * 125];
__device__ int    g_rowptr[N_NODES + 1];
__device__ int    g_pos  [N_NODES];
__device__ int    g_ssort[N_EDGES];
__device__ int    g_rsort[N_EDGES];

__constant__ int d_PL1[15] = {0,0,0,1,1,1,1,1,1,2,2,2,2,2,2};
__constant__ int d_PL2[15] = {0,1,2,0,1,1,1,2,2,0,1,1,2,2,2};
__constant__ int d_PL3[15] = {0,1,2,1,0,1,2,1,2,2,1,2,0,1,2};

#define LOFF0 0
#define LOFF1 1
#define LOFF2 4

// ---------------- packed f32x2 helpers ----------------
__device__ __forceinline__ unsigned long long pack_splat(float v){
    unsigned long long r;
    asm("mov.b64 %0, {%1, %1};" : "=l"(r) : "f"(v));
    return r;
}
__device__ __forceinline__ unsigned long long pack_f2(float2 v){
    unsigned long long r;
    asm("mov.b64 %0, {%1, %2};" : "=l"(r) : "f"(v.x), "f"(v.y));
    return r;
}
__device__ __forceinline__ void fma2(unsigned long long& d, unsigned long long a, unsigned long long b){
    asm("fma.rn.f32x2 %0, %1, %2, %0;" : "+l"(d) : "l"(a), "l"(b));
}
__device__ __forceinline__ void unpack2(float& lo, float& hi, unsigned long long v){
    asm("mov.b64 {%0, %1}, %2;" : "=f"(lo), "=f"(hi) : "l"(v));
}

// ---------------- CG tensors (exact replica, PARALLELIZED) --------
__device__ double dfact(int n){ double r=1.0; for(int i=2;i<=n;i++) r*=(double)i; return r; }

__device__ double cgsc(int j1,int m1,int j2,int m2,int j3,int m3){
    if (m1+m2 != m3) return 0.0;
    double pre = sqrt((2.0*j3+1.0)*dfact(j1+j2-j3)*dfact(j1-j2+j3)*dfact(-j1+j2+j3)/dfact(j1+j2+j3+1));
    pre *= sqrt(dfact(j1+m1)*dfact(j1-m1)*dfact(j2+m2)*dfact(j2-m2)*dfact(j3+m3)*dfact(j3-m3));
    int kmin = 0;
    if (j2-j3-m1 > kmin) kmin = j2-j3-m1;
    if (j1+m2-j3 > kmin) kmin = j1+m2-j3;
    int kmax = j1+j2-j3;
    if (j1-m1 < kmax) kmax = j1-m1;
    if (j2+m2 < kmax) kmax = j2+m2;
    double s = 0.0;
    for (int k=kmin; k<=kmax; k++){
        double den = dfact(k)*dfact(j1+j2-j3-k)*dfact(j1-m1-k)*dfact(j2+m2-k)
                   * dfact(j3-j2+m1+k)*dfact(j3-j1-m2+k);
        s += ((k & 1) ? -1.0 : 1.0) / den;
    }
    return pre * s;
}

__device__ void build_u(int l, double* ur, double* ui){
    int n = 2*l+1;
    for (int i=0;i<n*n;i++){ ur[i]=0.0; ui[i]=0.0; }
    double s2 = sqrt(0.5);
    for (int m=-l; m<=l; m++){
        if (m > 0){
            ur[(m+l)*n + ( m+l)] = ((m&1) ? -1.0 : 1.0) * s2;
            ur[(m+l)*n + (-m+l)] = s2;
        } else if (m == 0){
            ur[l*n + l] = 1.0;
        } else {
            ui[(m+l)*n + ( m+l)] = s2;
            ui[(m+l)*n + (-m+l)] = -(((-m)&1) ? -1.0 : 1.0) * s2;
        }
    }
}

// blocks 0..14: one per path; blocks 15..: zero g_pos
__global__ void __launch_bounds__(128)
cg_zero_kernel(){
    if (blockIdx.x >= NPATHS){
        int i = (blockIdx.x - NPATHS)*128 + threadIdx.x;
        if (i < N_NODES) g_pos[i] = 0;
        return;
    }
    int p = blockIdx.x;
    int tid = threadIdx.x;
    int lane = tid & 31, w = tid >> 5;
    int l1=d_PL1[p], l2=d_PL2[p], l3=d_PL3[p];
    int n1=2*l1+1, n2=2*l2+1, n3=2*l3+1;
    int nel = n1*n2*n3;

    __shared__ double s_cc[125];
    __shared__ double s_u1r[25], s_u1i[25], s_u2r[25], s_u2i[25], s_u3r[25], s_u3i[25];
    __shared__ double s_red[4][2];
    __shared__ double s_scale;
    __shared__ int    s_usere;

    if (tid == 0){
        build_u(l1, s_u1r, s_u1i);
        build_u(l2, s_u2r, s_u2i);
        build_u(l3, s_u3r, s_u3i);
    }
    if (tid < nel){
        int a = tid / (n2*n3), rem = tid % (n2*n3);
        int b = rem / n3, c = rem % n3;
        s_cc[(a*5+b)*5+c] = cgsc(l1, a-l1, l2, b-l2, l3, c-l3);
    }
    for (int t = tid; t < 125; t += 128) g_cg[p*125 + t] = 0.f;
    __syncthreads();

    double wr = 0.0, wi = 0.0;
    int i=0, j=0, k=0;
    if (tid < nel){
        i = tid / (n2*n3); int rem = tid % (n2*n3); j = rem / n3; k = rem % n3;
        for (int a=0;a<n1;a++){
            double ar = s_u1r[i*n1+a], ai = -s_u1i[i*n1+a];
            if (ar==0.0 && ai==0.0) continue;
            for (int b=0;b<n2;b++){
                double br = s_u2r[j*n2+b], bi = -s_u2i[j*n2+b];
                if (br==0.0 && bi==0.0) continue;
                double pr = ar*br - ai*bi, pi = ar*bi + ai*br;
                for (int c=0;c<n3;c++){
                    double cv = s_cc[(a*5+b)*5+c];
                    if (cv == 0.0) continue;
                    double cr = s_u3r[k*n3+c], ci = s_u3i[k*n3+c];
                    wr += (pr*cr - pi*ci) * cv;
                    wi += (pr*ci + pi*cr) * cv;
                }
            }
        }
    }

    double nr = wr*wr, ni = wi*wi;
    #pragma unroll
    for (int off=16; off>0; off>>=1){
        nr += __shfl_down_sync(0xffffffff, nr, off);
        ni += __shfl_down_sync(0xffffffff, ni, off);
    }
    if (lane == 0){ s_red[w][0] = nr; s_red[w][1] = ni; }
    __syncthreads();
    if (tid == 0){
        double tr = s_red[0][0] + s_red[1][0] + s_red[2][0] + s_red[3][0];
        double ti = s_red[0][1] + s_red[1][1] + s_red[2][1] + s_red[3][1];
        tr = sqrt(tr); ti = sqrt(ti);
        int use_re = (tr >= ti);
        s_usere = use_re;
        s_scale = sqrt((double)n3) / (use_re ? tr : ti);
    }
    __syncthreads();

    if (tid < nel){
        double v = (s_usere ? wr : wi) * s_scale;
        g_cg[p*125 + i*25 + j*5 + k] = (float)v;
    }
}

// ---------------- multi-block CSR build ----------------
__global__ void csr_count(const int* __restrict__ rcv){
    int e = blockIdx.x*blockDim.x + threadIdx.x;
    if (e < N_EDGES) atomicAdd(&g_pos[rcv[e]], 1);
}

__global__ void csr_scan(){
    __shared__ int sh[256];
    int t = threadIdx.x;
    int base = t*32;
    int tot = 0;
    #pragma unroll
    for (int i=0;i<32;i++) tot += g_pos[base+i];
    sh[t] = tot;
    __syncthreads();
    #pragma unroll
    for (int d=1; d<256; d<<=1){
        int v = (t>=d) ? sh[t-d] : 0;
        __syncthreads();
        sh[t] += v;
        __syncthreads();
    }
    int run = sh[t] - tot;
    for (int i=0;i<32;i++){
        int cnt = g_pos[base+i];
        g_rowptr[base+i] = run;
        g_pos[base+i] = run;
        run += cnt;
    }
    if (t == 255) g_rowptr[N_NODES] = N_EDGES;
}

__global__ void csr_scatter(const int* __restrict__ snd, const int* __restrict__ rcv){
    int e = blockIdx.x*blockDim.x + threadIdx.x;
    if (e >= N_EDGES) return;
    int r = rcv[e];
    int idx = atomicAdd(&g_pos[r], 1);
    g_ssort[idx] = snd[e];
    g_rsort[idx] = r;
}

// ---------------- geometry + A tensors + node init (smem-cached CG) ----------------
#define GEO_BLOCKS  (N_EDGES/256)
#define INIT_BLOCKS (N_NODES*C_DIM/256)

__global__ void geo_init_kernel(const float* __restrict__ pos,
                                const int* __restrict__ species,
                                const float* __restrict__ embed,
                                const float* __restrict__ w_proj){
    if (blockIdx.x < GEO_BLOCKS){
        __shared__ float s_cg[NPATHS*125];
        for (int i = threadIdx.x; i < NPATHS*125; i += 256) s_cg[i] = g_cg[i];
        __syncthreads();

        int s = blockIdx.x*256 + threadIdx.x;
        int sn = g_ssort[s], rn = g_rsort[s];
        float rx = (pos[rn*3+0]-pos[sn*3+0])*0.2f;
        float ry = (pos[rn*3+1]-pos[sn*3+1])*0.2f;
        float rz = (pos[rn*3+2]-pos[sn*3+2])*0.2f;
        float d  = sqrtf(rx*rx+ry*ry+rz*rz);
        float inv = 1.f/fmaxf(d, 1e-6f);
        float x=rx*inv, y=ry*inv, z=rz*inv;
        const float s3  = 1.7320508075688772f;
        const float s15 = 3.8729833462074170f;
        const float s5h = 1.1180339887498949f;
        float shv[9];
        shv[0]=1.f;
        shv[1]=s3*y; shv[2]=s3*z; shv[3]=s3*x;
        shv[4]=s15*x*y; shv[5]=s15*y*z; shv[6]=s5h*(3.f*z*z-1.f); shv[7]=s15*x*z; shv[8]=0.5f*s15*(x*x-y*y);
        float* g = &g_geo[s*18];
        #pragma unroll
        for (int t=0;t<9;t++) g[t]=shv[t];
        float xr = fminf(fmaxf(d, 1e-4f), 1.f);
        float invxr = 1.f/xr;
        const float pi = 3.14159265358979323846f;
        const float s2 = 1.4142135623730951f;
        #pragma unroll
        for (int q=0;q<8;q++) g[9+q] = s2 * __sinf((float)(q+1)*pi*xr) * invxr;
        float dc = fminf(fmaxf(d, 0.f), 1.f);
        g[17] = 0.5f*(__cosf(pi*dc)+1.f);

#define APATH(P, L1, L2, L3, AOF) {                                             \
        const float* cg = &s_cg[(P)*125];                                       \
        const float* sh2 = &shv[LOFF##L2];                                      \
        _Pragma("unroll")                                                       \
        for (int i=0;i<2*(L1)+1;i++){                                           \
            _Pragma("unroll")                                                   \
            for (int k=0;k<2*(L3)+1;k++){                                       \
                float t = 0.f;                                                  \
                _Pragma("unroll")                                               \
                for (int j=0;j<2*(L2)+1;j++) t += sh2[j]*cg[i*25 + j*5 + k];    \
                g_Af[((AOF) + i*(2*(L3)+1) + k)*N_EDGES + s] = t; } } }

        APATH(0 ,0,0,0,0)
        APATH(1 ,0,1,1,1)
        APATH(2 ,0,2,2,4)
        APATH(3 ,1,0,1,9)
        APATH(4 ,1,1,0,18)
        APATH(5 ,1,1,1,21)
        APATH(6 ,1,1,2,30)
        APATH(7 ,1,2,1,45)
        APATH(8 ,1,2,2,54)
        APATH(9 ,2,0,2,69)
        APATH(10,2,1,1,94)
        APATH(11,2,1,2,109)
        APATH(12,2,2,0,134)
        APATH(13,2,2,1,139)
        APATH(14,2,2,2,154)
#undef APATH
    } else {
        int idx = (blockIdx.x - GEO_BLOCKS)*256 + threadIdx.x;
        int n = idx >> 6, c = idx & 63;
        int sp = species[n];
        float acc = 0.f;
        #pragma unroll
        for (int j=0;j<32;j++) acc += embed[sp*32+j]*w_proj[j*64+c];
        float* f = &g_feat[n*FSTRIDE];
        f[c] = acc;
        #pragma unroll
        for (int t=1;t<9;t++) f[t*64+c] = 0.f;
    }
}

// ---------------- fused radial-MLP + GEMM (fp16 smem tiles, f32x2 accum) -------
// smem bytes: s_h1[128*68]f =34816 | s_h2h[64*136]h =17408 | s_bh[64*64]h =8192 | s_bas[128*9]f =4608
#define SMB_H1   0
#define SMB_H2H  34816
#define SMB_BH   52224
#define SMB_BAS  60416
#define WG_SMEM  (60416 + 4608)

__global__ void __launch_bounds__(256)
wgemm_fused(const float* __restrict__ w1, const float* __restrict__ b1,
            const float* __restrict__ w2, const float* __restrict__ b2,
            const float* __restrict__ w3){
    extern __shared__ char smraw[];
    float*  s_h1  = (float*)(smraw + SMB_H1);    // [e][c] pitch 68
    __half* s_h2h = (__half*)(smraw + SMB_H2H);  // [k][e] pitch 136 halves
    __half* s_bh  = (__half*)(smraw + SMB_BH);   // [k][n] 64x64 halves
    float*  s_bas = (float*)(smraw + SMB_BAS);   // [e][r] pitch 9

    int tid = threadIdx.x;
    int m0 = blockIdx.x * 128;

    for (int i = tid; i < 128*8; i += 256){
        int e = i >> 3, r = i & 7;
        s_bas[e*9 + r] = g_geo[(m0+e)*18 + 9 + r];
    }
    __syncthreads();

    // h1 = silu(basis @ w1 + b1)
    {
        int e = tid & 127;
        #pragma unroll
        for (int it=0; it<32; it++){
            int c = 2*it + (tid >> 7);
            float acc = b1[c];
            #pragma unroll
            for (int r=0;r<8;r++) acc += s_bas[e*9+r]*w1[r*64+c];
            s_h1[e*68 + c] = acc/(1.f+__expf(-acc));
        }
    }
    __syncthreads();

    // h2 = silu(h1 @ w2 + b2) -> fp16 transposed [k][e]
    {
        int c = tid >> 2, a = tid & 3;
        float w2c[64];
        #pragma unroll 16
        for (int r=0;r<64;r++) w2c[r] = w2[r*64 + c];
        float b2c = b2[c];
        #pragma unroll 4
        for (int j=0;j<32;j++){
            int e = 4*j + a;
            const float4* h1p = (const float4*)&s_h1[e*68];
            float acc = b2c;
            #pragma unroll
            for (int q=0;q<16;q++){
                float4 h4 = h1p[q];
                acc += h4.x*w2c[4*q] + h4.y*w2c[4*q+1] + h4.z*w2c[4*q+2] + h4.w*w2c[4*q+3];
            }
            s_h2h[c*136 + e] = __float2half(acc/(1.f+__expf(-acc)));
        }
    }
    __syncthreads();

    int r  = tid >> 4;       // 0..15 -> m = r*8
    int cl = tid & 15;       // 0..15 -> n = cl*4
    float cutv[8];
    #pragma unroll
    for (int i=0;i<8;i++) cutv[i] = g_geo[(m0 + r*8 + i)*18 + 17];

    for (int nt=0; nt<15; nt++){
        int n0 = nt*64;
        __syncthreads();
        // B tile fp32 global -> fp16 smem
        for (int i = tid; i < 512; i += 256){
            int k = i >> 3, n8 = (i & 7) << 3;
            float4 f0 = *(const float4*)&w3[k*960 + n0 + n8];
            float4 f1 = *(const float4*)&w3[k*960 + n0 + n8 + 4];
            __half2 h[4];
            h[0] = __floats2half2_rn(f0.x, f0.y);
            h[1] = __floats2half2_rn(f0.z, f0.w);
            h[2] = __floats2half2_rn(f1.x, f1.y);
            h[3] = __floats2half2_rn(f1.z, f1.w);
            *(uint4*)&s_bh[k*64 + n8] = *(uint4*)h;
        }
        __syncthreads();

        unsigned long long acc2[4][4];
        #pragma unroll
        for (int i=0;i<4;i++)
            #pragma unroll
            for (int j=0;j<4;j++) acc2[i][j] = 0ull;

        #pragma unroll 8
        for (int k=0;k<64;k++){
            uint2 braw = *(uint2*)&s_bh[k*64 + cl*4];
            float2 b01 = __half22float2(*(__half2*)&braw.x);
            float2 b23 = __half22float2(*(__half2*)&braw.y);
            unsigned long long bs0 = pack_splat(b01.x);
            unsigned long long bs1 = pack_splat(b01.y);
            unsigned long long bs2 = pack_splat(b23.x);
            unsigned long long bs3 = pack_splat(b23.y);
            uint4 araw = *(uint4*)&s_h2h[k*136 + r*8];
            unsigned long long ap0 = pack_f2(__half22float2(*(__half2*)&araw.x));
            unsigned long long ap1 = pack_f2(__half22float2(*(__half2*)&araw.y));
            unsigned long long ap2 = pack_f2(__half22float2(*(__half2*)&araw.z));
            unsigned long long ap3 = pack_f2(__half22float2(*(__half2*)&araw.w));
            fma2(acc2[0][0], ap0, bs0); fma2(acc2[0][1], ap0, bs1);
            fma2(acc2[0][2], ap0, bs2); fma2(acc2[0][3], ap0, bs3);
            fma2(acc2[1][0], ap1, bs0); fma2(acc2[1][1], ap1, bs1);
            fma2(acc2[1][2], ap1, bs2); fma2(acc2[1][3], ap1, bs3);
            fma2(acc2[2][0], ap2, bs0); fma2(acc2[2][1], ap2, bs1);
            fma2(acc2[2][2], ap2, bs2); fma2(acc2[2][3], ap2, bs3);
            fma2(acc2[3][0], ap3, bs0); fma2(acc2[3][1], ap3, bs1);
            fma2(acc2[3][2], ap3, bs2); fma2(acc2[3][3], ap3, bs3);
        }

        #pragma unroll
        for (int mp=0; mp<4; mp++){
            float v0[4], v1[4];
            #pragma unroll
            for (int j=0;j<4;j++) unpack2(v0[j], v1[j], acc2[mp][j]);
            int mA = m0 + r*8 + 2*mp;
            float c0 = cutv[2*mp], c1 = cutv[2*mp+1];
            __half2* dstA = (__half2*)&g_w[(size_t)mA*960 + n0 + cl*4];
            __half2* dstB = (__half2*)&g_w[(size_t)(mA+1)*960 + n0 + cl*4];
            dstA[0] = __floats2half2_rn(v0[0]*c0, v0[1]*c0);
            dstA[1] = __floats2half2_rn(v0[2]*c0, v0[3]*c0);
            dstB[0] = __floats2half2_rn(v1[0]*c1, v1[1]*c1);
            dstB[1] = __floats2half2_rn(v1[2]*c1, v1[3]*c1);
        }
    }
}

// ---------------- fused message + gather-reduce + node update ----------------
__global__ void __launch_bounds__(256)
node_fused(const float* __restrict__ lin_self, const float* __restrict__ gate_w,
           const float* __restrict__ gate_b, int layer){
    int n = blockIdx.x;
    int tid = threadIdx.x;
    int warp = tid >> 5, lane = tid & 31;
    int slotb = warp >> 1, chalf = warp & 1;
    int c = chalf*32 + lane;

    const float* xin  = (layer == 0) ? g_feat  : g_feat2;
    float*       xout = (layer == 0) ? g_feat2 : g_feat;

    __shared__ float s_A[8][192];
    __shared__ int   s_sn[8];
    __shared__ float s_red[8][9][32];
    __shared__ float sa[576];
    __shared__ float s_f0[64];

    int beg = g_rowptr[n], end = g_rowptr[n+1];

    float a[9];
    #pragma unroll
    for (int t=0;t<9;t++) a[t]=0.f;

    for (int s0 = beg; s0 < end; s0 += 8){
        int ne = end - s0; if (ne > 8) ne = 8;
        __syncthreads();
        for (int idx = tid; idx < 192*ne; idx += 256){
            int j = idx / ne, slot = idx - j*ne;
            s_A[slot][j] = g_Af[j*N_EDGES + s0 + slot];
        }
        if (tid < ne) s_sn[tid] = g_ssort[s0 + tid];
        __syncthreads();

        #pragma unroll
        for (int sub=0; sub<2; sub++){
            int slot = slotb + sub*4;
            if (slot < ne){
                int s  = s0 + slot;
                int sn = s_sn[slot];
                const __half* wrow = &g_w[(size_t)s*960];
                const float*  xrow = &xin[sn*FSTRIDE];
                float x[9], m[9];
                #pragma unroll
                for (int t=0;t<9;t++){ x[t] = xrow[t*64 + c]; m[t] = 0.f; }

#define MSG_PATH(P, L1, L3, AOF) {                                              \
                float wpc = __half2float(wrow[(P)*64 + c]);                     \
                const float* Ap = &s_A[slot][(AOF)];                            \
                _Pragma("unroll")                                               \
                for (int k=0;k<2*(L3)+1;k++){                                   \
                    float t = 0.f;                                              \
                    _Pragma("unroll")                                           \
                    for (int i=0;i<2*(L1)+1;i++) t += x[LOFF##L1 + i]*Ap[i*(2*(L3)+1)+k]; \
                    m[LOFF##L3 + k] += wpc*t; } }

                MSG_PATH(0 ,0,0,0)
                MSG_PATH(1 ,0,1,1)
                MSG_PATH(2 ,0,2,4)
                MSG_PATH(3 ,1,1,9)
                MSG_PATH(4 ,1,0,18)
                MSG_PATH(5 ,1,1,21)
                MSG_PATH(6 ,1,2,30)
                MSG_PATH(7 ,1,1,45)
                MSG_PATH(8 ,1,2,54)
                MSG_PATH(9 ,2,2,69)
                MSG_PATH(10,2,1,94)
                MSG_PATH(11,2,2,109)
                MSG_PATH(12,2,0,134)
                MSG_PATH(13,2,1,139)
                MSG_PATH(14,2,2,154)
#undef MSG_PATH

                #pragma unroll
                for (int t=0;t<9;t++) a[t] += m[t];
            }
        }
    }

    #pragma unroll
    for (int t=0;t<9;t++) s_red[warp][t][lane] = a[t];
    __syncthreads();

    if (tid < 64){
        int cc = tid, h = cc >> 5, l = cc & 31;
        #pragma unroll
        for (int t=0;t<9;t++)
            sa[t*64+cc] = 0.25f*(s_red[h][t][l] + s_red[h+2][t][l] + s_red[h+4][t][l] + s_red[h+6][t][l]);
    }
    __syncthreads();

    if (tid < 64){
        int cc = tid;
        const float* lin0 = lin_self + (layer*3+0)*4096;
        const float* lin1 = lin_self + (layer*3+1)*4096;
        const float* lin2 = lin_self + (layer*3+2)*4096;
        float y[9];
        #pragma unroll
        for (int k=0;k<9;k++) y[k]=0.f;
        for (int q=0; q<64; q++){
            float w0 = lin0[q*64+cc], w1v = lin1[q*64+cc], w2v = lin2[q*64+cc];
            y[0]+=sa[0*64+q]*w0;
            y[1]+=sa[1*64+q]*w1v; y[2]+=sa[2*64+q]*w1v; y[3]+=sa[3*64+q]*w1v;
            y[4]+=sa[4*64+q]*w2v; y[5]+=sa[5*64+q]*w2v; y[6]+=sa[6*64+q]*w2v;
            y[7]+=sa[7*64+q]*w2v; y[8]+=sa[8*64+q]*w2v;
        }
        const float* fin  = &xin [n*FSTRIDE];
        float*       fout = &xout[n*FSTRIDE];
        float f0v = fin[cc] + y[0]/(1.f+__expf(-y[0]));
        fout[cc] = f0v; s_f0[cc] = f0v;
        __syncwarp();
        __syncthreads();
        const float* gw1 = gate_w + (layer*2+0)*4096;
        const float* gw2 = gate_w + (layer*2+1)*4096;
        float s1 = gate_b[(layer*2+0)*64 + cc];
        float s2 = gate_b[(layer*2+1)*64 + cc];
        for (int q=0; q<64; q++){
            float fc = s_f0[q];
            s1 += fc*gw1[q*64+cc];
            s2 += fc*gw2[q*64+cc];
        }
        float g1 = 1.f/(1.f+__expf(-s1));
        float g2 = 1.f/(1.f+__expf(-s2));
        #pragma unroll
        for (int t=1;t<4;t++) fout[t*64+cc] = fin[t*64+cc] + g1*y[t];
        #pragma unroll
        for (int t=4;t<9;t++) fout[t*64+cc] = fin[t*64+cc] + g2*y[t];
    } else {
        __syncthreads();
    }
}

// ---------------- output assembly ----------------
__global__ void out_kernel(float* __restrict__ out){
    int idx = blockIdx.x*blockDim.x + threadIdx.x;
    if (idx >= N_NODES*576) return;
    int n = idx/576, j = idx%576;
    float v;
    if (j < 64)       v =        g_feat[n*FSTRIDE + j];
    else if (j < 256){ int jj=j-64;  v = 0.5f  * g_feat[n*FSTRIDE + (1+jj%3)*64 + jj/3]; }
    else             { int jj=j-256; v = 0.25f * g_feat[n*FSTRIDE + (4+jj%5)*64 + jj/5]; }
    out[idx] = v;
}

// ---------------- launch ----------------
extern "C" void kernel_launch(void* const* d_in, const int* in_sizes, int n_in,
                              void* d_out, int out_size){
    const float* positions = (const float*)d_in[0];
    const int*   species   = (const int*)  d_in[1];
    const int*   senders   = (const int*)  d_in[2];
    const int*   receivers = (const int*)  d_in[3];
    const float* embed     = (const float*)d_in[4];
    const float* w_proj    = (const float*)d_in[5];
    const float* mlp_w1    = (const float*)d_in[6];
    const float* mlp_b1    = (const float*)d_in[7];
    const float* mlp_w2    = (const float*)d_in[8];
    const float* mlp_b2    = (const float*)d_in[9];
    const float* mlp_w3    = (const float*)d_in[10];
    const float* lin_self  = (const float*)d_in[11];
    const float* gate_w    = (const float*)d_in[12];
    const float* gate_b    = (const float*)d_in[13];
    float* out = (float*)d_out;

    cudaFuncSetAttribute(wgemm_fused, cudaFuncAttributeMaxDynamicSharedMemorySize, WG_SMEM);

    cg_zero_kernel<<<NPATHS + N_NODES/128, 128>>>();             // launch 0
    csr_count<<<N_EDGES/256, 256>>>(receivers);                  // launch 1
    csr_scan<<<1, 256>>>();                                      // launch 2
    csr_scatter<<<N_EDGES/256, 256>>>(senders, receivers);       // launch 3 (profiled)
    geo_init_kernel<<<GEO_BLOCKS + INIT_BLOCKS, 256>>>(          // launch 4
        positions, species, embed, w_proj);

    for (int L=0; L<2; L++){
        wgemm_fused<<<N_EDGES/128, 256, WG_SMEM>>>(              // launch 5, 7
            mlp_w1 + L*8*64,  mlp_b1 + L*64,
            mlp_w2 + L*64*64, mlp_b2 + L*64,
            mlp_w3 + L*64*960);
        node_fused<<<N_NODES, 256>>>(lin_self, gate_w, gate_b, L);  // launch 6, 8
    }
    out_kernel<<<(N_NODES*576)/256, 256>>>(out);                 // launch 9
}

// round 14
// speedup vs baseline: 1.1623x; 1.1623x over previous
#include <cuda_runtime.h>
#include <cuda_fp16.h>
#include <cstdint>
#include <math.h>

#define N_NODES   8192
#define N_EDGES   131072
#define C_DIM     64
#define NPATHS    15
#define FSTRIDE   576

// ---------------- device scratch ----------------
__device__ float  g_feat [N_NODES * FSTRIDE];    // ping  [n][t][c]
__device__ float  g_feat2[N_NODES * FSTRIDE];    // pong
__device__ float  g_geo  [N_EDGES * 18];         // sorted: sh[9], basis[8], cut
__device__ float  g_Af   [192 * N_EDGES];        // sorted: A tensors, [elem][edge] scalar SoA
__device__ __half g_w    [N_EDGES * 960];        // sorted: edge tp weights (fp16)
__device__ float  g_cg   [NPATHS * 125];
__device__ int    g_rowptr[N_NODES + 1];
__device__ int    g_pos  [N_NODES];
__device__ int    g_ssort[N_EDGES];
__device__ int    g_rsort[N_EDGES];

__constant__ int d_PL1[15] = {0,0,0,1,1,1,1,1,1,2,2,2,2,2,2};
__constant__ int d_PL2[15] = {0,1,2,0,1,1,1,2,2,0,1,1,2,2,2};
__constant__ int d_PL3[15] = {0,1,2,1,0,1,2,1,2,2,1,2,0,1,2};

#define LOFF0 0
#define LOFF1 1
#define LOFF2 4

// ---------------- packed f32x2 helpers ----------------
__device__ __forceinline__ unsigned long long pack_splat(float v){
    unsigned long long r;
    asm("mov.b64 %0, {%1, %1};" : "=l"(r) : "f"(v));
    return r;
}
__device__ __forceinline__ void fma2(unsigned long long& d, unsigned long long a, unsigned long long b){
    asm("fma.rn.f32x2 %0, %1, %2, %0;" : "+l"(d) : "l"(a), "l"(b));
}
__device__ __forceinline__ void unpack2(float& lo, float& hi, unsigned long long v){
    asm("mov.b64 {%0, %1}, %2;" : "=f"(lo), "=f"(hi) : "l"(v));
}

// ---------------- CG tensors (exact replica, PARALLELIZED) --------
__device__ double dfact(int n){ double r=1.0; for(int i=2;i<=n;i++) r*=(double)i; return r; }

__device__ double cgsc(int j1,int m1,int j2,int m2,int j3,int m3){
    if (m1+m2 != m3) return 0.0;
    double pre = sqrt((2.0*j3+1.0)*dfact(j1+j2-j3)*dfact(j1-j2+j3)*dfact(-j1+j2+j3)/dfact(j1+j2+j3+1));
    pre *= sqrt(dfact(j1+m1)*dfact(j1-m1)*dfact(j2+m2)*dfact(j2-m2)*dfact(j3+m3)*dfact(j3-m3));
    int kmin = 0;
    if (j2-j3-m1 > kmin) kmin = j2-j3-m1;
    if (j1+m2-j3 > kmin) kmin = j1+m2-j3;
    int kmax = j1+j2-j3;
    if (j1-m1 < kmax) kmax = j1-m1;
    if (j2+m2 < kmax) kmax = j2+m2;
    double s = 0.0;
    for (int k=kmin; k<=kmax; k++){
        double den = dfact(k)*dfact(j1+j2-j3-k)*dfact(j1-m1-k)*dfact(j2+m2-k)
                   * dfact(j3-j2+m1+k)*dfact(j3-j1-m2+k);
        s += ((k & 1) ? -1.0 : 1.0) / den;
    }
    return pre * s;
}

__device__ void build_u(int l, double* ur, double* ui){
    int n = 2*l+1;
    for (int i=0;i<n*n;i++){ ur[i]=0.0; ui[i]=0.0; }
    double s2 = sqrt(0.5);
    for (int m=-l; m<=l; m++){
        if (m > 0){
            ur[(m+l)*n + ( m+l)] = ((m&1) ? -1.0 : 1.0) * s2;
            ur[(m+l)*n + (-m+l)] = s2;
        } else if (m == 0){
            ur[l*n + l] = 1.0;
        } else {
            ui[(m+l)*n + ( m+l)] = s2;
            ui[(m+l)*n + (-m+l)] = -(((-m)&1) ? -1.0 : 1.0) * s2;
        }
    }
}

// blocks 0..14: one per path; blocks 15..: zero g_pos
__global__ void __launch_bounds__(128)
cg_zero_kernel(){
    if (blockIdx.x >= NPATHS){
        int i = (blockIdx.x - NPATHS)*128 + threadIdx.x;
        if (i < N_NODES) g_pos[i] = 0;
        return;
    }
    int p = blockIdx.x;
    int tid = threadIdx.x;
    int lane = tid & 31, w = tid >> 5;
    int l1=d_PL1[p], l2=d_PL2[p], l3=d_PL3[p];
    int n1=2*l1+1, n2=2*l2+1, n3=2*l3+1;
    int nel = n1*n2*n3;

    __shared__ double s_cc[125];
    __shared__ double s_u1r[25], s_u1i[25], s_u2r[25], s_u2i[25], s_u3r[25], s_u3i[25];
    __shared__ double s_red[4][2];
    __shared__ double s_scale;
    __shared__ int    s_usere;

    if (tid == 0){
        build_u(l1, s_u1r, s_u1i);
        build_u(l2, s_u2r, s_u2i);
        build_u(l3, s_u3r, s_u3i);
    }
    if (tid < nel){
        int a = tid / (n2*n3), rem = tid % (n2*n3);
        int b = rem / n3, c = rem % n3;
        s_cc[(a*5+b)*5+c] = cgsc(l1, a-l1, l2, b-l2, l3, c-l3);
    }
    for (int t = tid; t < 125; t += 128) g_cg[p*125 + t] = 0.f;
    __syncthreads();

    double wr = 0.0, wi = 0.0;
    int i=0, j=0, k=0;
    if (tid < nel){
        i = tid / (n2*n3); int rem = tid % (n2*n3); j = rem / n3; k = rem % n3;
        for (int a=0;a<n1;a++){
            double ar = s_u1r[i*n1+a], ai = -s_u1i[i*n1+a];
            if (ar==0.0 && ai==0.0) continue;
            for (int b=0;b<n2;b++){
                double br = s_u2r[j*n2+b], bi = -s_u2i[j*n2+b];
                if (br==0.0 && bi==0.0) continue;
                double pr = ar*br - ai*bi, pi = ar*bi + ai*br;
                for (int c=0;c<n3;c++){
                    double cv = s_cc[(a*5+b)*5+c];
                    if (cv == 0.0) continue;
                    double cr = s_u3r[k*n3+c], ci = s_u3i[k*n3+c];
                    wr += (pr*cr - pi*ci) * cv;
                    wi += (pr*ci + pi*cr) * cv;
                }
            }
        }
    }

    double nr = wr*wr, ni = wi*wi;
    #pragma unroll
    for (int off=16; off>0; off>>=1){
        nr += __shfl_down_sync(0xffffffff, nr, off);
        ni += __shfl_down_sync(0xffffffff, ni, off);
    }
    if (lane == 0){ s_red[w][0] = nr; s_red[w][1] = ni; }
    __syncthreads();
    if (tid == 0){
        double tr = s_red[0][0] + s_red[1][0] + s_red[2][0] + s_red[3][0];
        double ti = s_red[0][1] + s_red[1][1] + s_red[2][1] + s_red[3][1];
        tr = sqrt(tr); ti = sqrt(ti);
        int use_re = (tr >= ti);
        s_usere = use_re;
        s_scale = sqrt((double)n3) / (use_re ? tr : ti);
    }
    __syncthreads();

    if (tid < nel){
        double v = (s_usere ? wr : wi) * s_scale;
        g_cg[p*125 + i*25 + j*5 + k] = (float)v;
    }
}

// ---------------- multi-block CSR build ----------------
__global__ void csr_count(const int* __restrict__ rcv){
    int e = blockIdx.x*blockDim.x + threadIdx.x;
    if (e < N_EDGES) atomicAdd(&g_pos[rcv[e]], 1);
}

__global__ void csr_scan(){
    __shared__ int sh[256];
    int t = threadIdx.x;
    int base = t*32;
    int tot = 0;
    #pragma unroll
    for (int i=0;i<32;i++) tot += g_pos[base+i];
    sh[t] = tot;
    __syncthreads();
    #pragma unroll
    for (int d=1; d<256; d<<=1){
        int v = (t>=d) ? sh[t-d] : 0;
        __syncthreads();
        sh[t] += v;
        __syncthreads();
    }
    int run = sh[t] - tot;
    for (int i=0;i<32;i++){
        int cnt = g_pos[base+i];
        g_rowptr[base+i] = run;
        g_pos[base+i] = run;
        run += cnt;
    }
    if (t == 255) g_rowptr[N_NODES] = N_EDGES;
}

__global__ void csr_scatter(const int* __restrict__ snd, const int* __restrict__ rcv){
    int e = blockIdx.x*blockDim.x + threadIdx.x;
    if (e >= N_EDGES) return;
    int r = rcv[e];
    int idx = atomicAdd(&g_pos[r], 1);
    g_ssort[idx] = snd[e];
    g_rsort[idx] = r;
}

// ---------------- geometry + A tensors + node init (smem-cached CG) ----------------
#define GEO_BLOCKS  (N_EDGES/256)
#define INIT_BLOCKS (N_NODES*C_DIM/256)

__global__ void geo_init_kernel(const float* __restrict__ pos,
                                const int* __restrict__ species,
                                const float* __restrict__ embed,
                                const float* __restrict__ w_proj){
    if (blockIdx.x < GEO_BLOCKS){
        __shared__ float s_cg[NPATHS*125];
        for (int i = threadIdx.x; i < NPATHS*125; i += 256) s_cg[i] = g_cg[i];
        __syncthreads();

        int s = blockIdx.x*256 + threadIdx.x;
        int sn = g_ssort[s], rn = g_rsort[s];
        float rx = (pos[rn*3+0]-pos[sn*3+0])*0.2f;
        float ry = (pos[rn*3+1]-pos[sn*3+1])*0.2f;
        float rz = (pos[rn*3+2]-pos[sn*3+2])*0.2f;
        float d  = sqrtf(rx*rx+ry*ry+rz*rz);
        float inv = 1.f/fmaxf(d, 1e-6f);
        float x=rx*inv, y=ry*inv, z=rz*inv;
        const float s3  = 1.7320508075688772f;
        const float s15 = 3.8729833462074170f;
        const float s5h = 1.1180339887498949f;
        float shv[9];
        shv[0]=1.f;
        shv[1]=s3*y; shv[2]=s3*z; shv[3]=s3*x;
        shv[4]=s15*x*y; shv[5]=s15*y*z; shv[6]=s5h*(3.f*z*z-1.f); shv[7]=s15*x*z; shv[8]=0.5f*s15*(x*x-y*y);
        float* g = &g_geo[s*18];
        #pragma unroll
        for (int t=0;t<9;t++) g[t]=shv[t];
        float xr = fminf(fmaxf(d, 1e-4f), 1.f);
        float invxr = 1.f/xr;
        const float pi = 3.14159265358979323846f;
        const float s2 = 1.4142135623730951f;
        #pragma unroll
        for (int q=0;q<8;q++) g[9+q] = s2 * __sinf((float)(q+1)*pi*xr) * invxr;
        float dc = fminf(fmaxf(d, 0.f), 1.f);
        g[17] = 0.5f*(__cosf(pi*dc)+1.f);

#define APATH(P, L1, L2, L3, AOF) {                                             \
        const float* cg = &s_cg[(P)*125];                                       \
        const float* sh2 = &shv[LOFF##L2];                                      \
        _Pragma("unroll")                                                       \
        for (int i=0;i<2*(L1)+1;i++){                                           \
            _Pragma("unroll")                                                   \
            for (int k=0;k<2*(L3)+1;k++){                                       \
                float t = 0.f;                                                  \
                _Pragma("unroll")                                               \
                for (int j=0;j<2*(L2)+1;j++) t += sh2[j]*cg[i*25 + j*5 + k];    \
                g_Af[((AOF) + i*(2*(L3)+1) + k)*N_EDGES + s] = t; } } }

        APATH(0 ,0,0,0,0)
        APATH(1 ,0,1,1,1)
        APATH(2 ,0,2,2,4)
        APATH(3 ,1,0,1,9)
        APATH(4 ,1,1,0,18)
        APATH(5 ,1,1,1,21)
        APATH(6 ,1,1,2,30)
        APATH(7 ,1,2,1,45)
        APATH(8 ,1,2,2,54)
        APATH(9 ,2,0,2,69)
        APATH(10,2,1,1,94)
        APATH(11,2,1,2,109)
        APATH(12,2,2,0,134)
        APATH(13,2,2,1,139)
        APATH(14,2,2,2,154)
#undef APATH
    } else {
        int idx = (blockIdx.x - GEO_BLOCKS)*256 + threadIdx.x;
        int n = idx >> 6, c = idx & 63;
        int sp = species[n];
        float acc = 0.f;
        #pragma unroll
        for (int j=0;j<32;j++) acc += embed[sp*32+j]*w_proj[j*64+c];
        float* f = &g_feat[n*FSTRIDE];
        f[c] = acc;
        #pragma unroll
        for (int t=1;t<9;t++) f[t*64+c] = 0.f;
    }
}

// ---------------- fused radial-MLP + GEMM (R8-exact: 8m x 4n f32x2) -------
// smem floats: s_h1[128*68]=8704 | s_h2[64*132]=8448 | s_b[64*64]=4096 | s_basis[128*9]=1152
#define SM_H1   0
#define SM_H2   8704
#define SM_B    17152
#define SM_BAS  21248
#define WG_SMEM (22400*4)

__global__ void __launch_bounds__(256)
wgemm_fused(const float* __restrict__ w1, const float* __restrict__ b1,
            const float* __restrict__ w2, const float* __restrict__ b2,
            const float* __restrict__ w3){
    extern __shared__ float sm[];
    float* s_h1  = sm + SM_H1;     // [e][c] pitch 68
    float* s_h2  = sm + SM_H2;     // [k][e] pitch 132
    float* s_b   = sm + SM_B;      // [k][n] 64x64
    float* s_bas = sm + SM_BAS;    // [e][r] pitch 9

    int tid = threadIdx.x;
    int m0 = blockIdx.x * 128;

    for (int i = tid; i < 128*8; i += 256){
        int e = i >> 3, r = i & 7;
        s_bas[e*9 + r] = g_geo[(m0+e)*18 + 9 + r];
    }
    __syncthreads();

    {
        int e = tid & 127;
        #pragma unroll
        for (int it=0; it<32; it++){
            int c = 2*it + (tid >> 7);
            float acc = b1[c];
            #pragma unroll
            for (int r=0;r<8;r++) acc += s_bas[e*9+r]*w1[r*64+c];
            s_h1[e*68 + c] = acc/(1.f+__expf(-acc));
        }
    }
    __syncthreads();

    {
        int c = tid >> 2, a = tid & 3;
        float w2c[64];
        #pragma unroll 16
        for (int r=0;r<64;r++) w2c[r] = w2[r*64 + c];
        float b2c = b2[c];
        #pragma unroll 4
        for (int j=0;j<32;j++){
            int e = 4*j + a;
            const float4* h1p = (const float4*)&s_h1[e*68];
            float acc = b2c;
            #pragma unroll
            for (int q=0;q<16;q++){
                float4 h4 = h1p[q];
                acc += h4.x*w2c[4*q] + h4.y*w2c[4*q+1] + h4.z*w2c[4*q+2] + h4.w*w2c[4*q+3];
            }
            s_h2[c*132 + e] = acc/(1.f+__expf(-acc));
        }
    }
    __syncthreads();

    int r  = tid >> 4;
    int cl = tid & 15;
    float cutv[8];
    #pragma unroll
    for (int i=0;i<8;i++) cutv[i] = g_geo[(m0 + r*8 + i)*18 + 17];

    for (int nt=0; nt<15; nt++){
        int n0 = nt*64;
        __syncthreads();
        #pragma unroll
        for (int i = tid; i < 64*64/4; i += 256){
            int k = i >> 4, n = (i & 15) << 2;
            *(float4*)&s_b[k*64 + n] = *(const float4*)&w3[k*960 + n0 + n];
        }
        __syncthreads();

        unsigned long long acc2[4][4];
        #pragma unroll
        for (int i=0;i<4;i++)
            #pragma unroll
            for (int j=0;j<4;j++) acc2[i][j] = 0ull;

        #pragma unroll 8
        for (int k=0;k<64;k++){
            float4 bf = *(float4*)&s_b[k*64 + cl*4];
            unsigned long long bs0 = pack_splat(bf.x);
            unsigned long long bs1 = pack_splat(bf.y);
            unsigned long long bs2 = pack_splat(bf.z);
            unsigned long long bs3 = pack_splat(bf.w);
            ulonglong2 ap0 = *(ulonglong2*)&s_h2[k*132 + r*8];
            ulonglong2 ap1 = *(ulonglong2*)&s_h2[k*132 + r*8 + 4];
            fma2(acc2[0][0], ap0.x, bs0); fma2(acc2[0][1], ap0.x, bs1);
            fma2(acc2[0][2], ap0.x, bs2); fma2(acc2[0][3], ap0.x, bs3);
            fma2(acc2[1][0], ap0.y, bs0); fma2(acc2[1][1], ap0.y, bs1);
            fma2(acc2[1][2], ap0.y, bs2); fma2(acc2[1][3], ap0.y, bs3);
            fma2(acc2[2][0], ap1.x, bs0); fma2(acc2[2][1], ap1.x, bs1);
            fma2(acc2[2][2], ap1.x, bs2); fma2(acc2[2][3], ap1.x, bs3);
            fma2(acc2[3][0], ap1.y, bs0); fma2(acc2[3][1], ap1.y, bs1);
            fma2(acc2[3][2], ap1.y, bs2); fma2(acc2[3][3], ap1.y, bs3);
        }

        #pragma unroll
        for (int mp=0; mp<4; mp++){
            float v0[4], v1[4];
            #pragma unroll
            for (int j=0;j<4;j++) unpack2(v0[j], v1[j], acc2[mp][j]);
            int mA = m0 + r*8 + 2*mp;
            float c0 = cutv[2*mp], c1 = cutv[2*mp+1];
            __half2* dstA = (__half2*)&g_w[(size_t)mA*960 + n0 + cl*4];
            __half2* dstB = (__half2*)&g_w[(size_t)(mA+1)*960 + n0 + cl*4];
            dstA[0] = __floats2half2_rn(v0[0]*c0, v0[1]*c0);
            dstA[1] = __floats2half2_rn(v0[2]*c0, v0[3]*c0);
            dstB[0] = __floats2half2_rn(v1[0]*c1, v1[1]*c1);
            dstB[1] = __floats2half2_rn(v1[2]*c1, v1[3]*c1);
        }
    }
}

// ---------------- fused message + gather-reduce + node update ----------------
__global__ void __launch_bounds__(256)
node_fused(const float* __restrict__ lin_self, const float* __restrict__ gate_w,
           const float* __restrict__ gate_b, int layer){
    int n = blockIdx.x;
    int tid = threadIdx.x;
    int warp = tid >> 5, lane = tid & 31;
    int slotb = warp >> 1, chalf = warp & 1;
    int c = chalf*32 + lane;

    const float* xin  = (layer == 0) ? g_feat  : g_feat2;
    float*       xout = (layer == 0) ? g_feat2 : g_feat;

    __shared__ float s_A[8][192];
    __shared__ int   s_sn[8];
    __shared__ float s_red[8][9][32];
    __shared__ float sa[576];
    __shared__ float s_f0[64];

    int beg = g_rowptr[n], end = g_rowptr[n+1];

    float a[9];
    #pragma unroll
    for (int t=0;t<9;t++) a[t]=0.f;

    for (int s0 = beg; s0 < end; s0 += 8){
        int ne = end - s0; if (ne > 8) ne = 8;
        __syncthreads();
        for (int idx = tid; idx < 192*ne; idx += 256){
            int j = idx / ne, slot = idx - j*ne;
            s_A[slot][j] = g_Af[j*N_EDGES + s0 + slot];
        }
        if (tid < ne) s_sn[tid] = g_ssort[s0 + tid];
        __syncthreads();

        #pragma unroll
        for (int sub=0; sub<2; sub++){
            int slot = slotb + sub*4;
            if (slot < ne){
                int s  = s0 + slot;
                int sn = s_sn[slot];
                const __half* wrow = &g_w[(size_t)s*960];
                const float*  xrow = &xin[sn*FSTRIDE];
                float x[9], m[9];
                #pragma unroll
                for (int t=0;t<9;t++){ x[t] = xrow[t*64 + c]; m[t] = 0.f; }

#define MSG_PATH(P, L1, L3, AOF) {                                              \
                float wpc = __half2float(wrow[(P)*64 + c]);                     \
                const float* Ap = &s_A[slot][(AOF)];                            \
                _Pragma("unroll")                                               \
                for (int k=0;k<2*(L3)+1;k++){                                   \
                    float t = 0.f;                                              \
                    _Pragma("unroll")                                           \
                    for (int i=0;i<2*(L1)+1;i++) t += x[LOFF##L1 + i]*Ap[i*(2*(L3)+1)+k]; \
                    m[LOFF##L3 + k] += wpc*t; } }

                MSG_PATH(0 ,0,0,0)
                MSG_PATH(1 ,0,1,1)
                MSG_PATH(2 ,0,2,4)
                MSG_PATH(3 ,1,1,9)
                MSG_PATH(4 ,1,0,18)
                MSG_PATH(5 ,1,1,21)
                MSG_PATH(6 ,1,2,30)
                MSG_PATH(7 ,1,1,45)
                MSG_PATH(8 ,1,2,54)
                MSG_PATH(9 ,2,2,69)
                MSG_PATH(10,2,1,94)
                MSG_PATH(11,2,2,109)
                MSG_PATH(12,2,0,134)
                MSG_PATH(13,2,1,139)
                MSG_PATH(14,2,2,154)
#undef MSG_PATH

                #pragma unroll
                for (int t=0;t<9;t++) a[t] += m[t];
            }
        }
    }

    #pragma unroll
    for (int t=0;t<9;t++) s_red[warp][t][lane] = a[t];
    __syncthreads();

    if (tid < 64){
        int cc = tid, h = cc >> 5, l = cc & 31;
        #pragma unroll
        for (int t=0;t<9;t++)
            sa[t*64+cc] = 0.25f*(s_red[h][t][l] + s_red[h+2][t][l] + s_red[h+4][t][l] + s_red[h+6][t][l]);
    }
    __syncthreads();

    if (tid < 64){
        int cc = tid;
        const float* lin0 = lin_self + (layer*3+0)*4096;
        const float* lin1 = lin_self + (layer*3+1)*4096;
        const float* lin2 = lin_self + (layer*3+2)*4096;
        float y[9];
        #pragma unroll
        for (int k=0;k<9;k++) y[k]=0.f;
        for (int q=0; q<64; q++){
            float w0 = lin0[q*64+cc], w1v = lin1[q*64+cc], w2v = lin2[q*64+cc];
            y[0]+=sa[0*64+q]*w0;
            y[1]+=sa[1*64+q]*w1v; y[2]+=sa[2*64+q]*w1v; y[3]+=sa[3*64+q]*w1v;
            y[4]+=sa[4*64+q]*w2v; y[5]+=sa[5*64+q]*w2v; y[6]+=sa[6*64+q]*w2v;
            y[7]+=sa[7*64+q]*w2v; y[8]+=sa[8*64+q]*w2v;
        }
        const float* fin  = &xin [n*FSTRIDE];
        float*       fout = &xout[n*FSTRIDE];
        float f0v = fin[cc] + y[0]/(1.f+__expf(-y[0]));
        fout[cc] = f0v; s_f0[cc] = f0v;
        __syncwarp();
        __syncthreads();
        const float* gw1 = gate_w + (layer*2+0)*4096;
        const float* gw2 = gate_w + (layer*2+1)*4096;
        float s1 = gate_b[(layer*2+0)*64 + cc];
        float s2 = gate_b[(layer*2+1)*64 + cc];
        for (int q=0; q<64; q++){
            float fc = s_f0[q];
            s1 += fc*gw1[q*64+cc];
            s2 += fc*gw2[q*64+cc];
        }
        float g1 = 1.f/(1.f+__expf(-s1));
        float g2 = 1.f/(1.f+__expf(-s2));
        #pragma unroll
        for (int t=1;t<4;t++) fout[t*64+cc] = fin[t*64+cc] + g1*y[t];
        #pragma unroll
        for (int t=4;t<9;t++) fout[t*64+cc] = fin[t*64+cc] + g2*y[t];
    } else {
        __syncthreads();
    }
}

// ---------------- output assembly ----------------
__global__ void out_kernel(float* __restrict__ out){
    int idx = blockIdx.x*blockDim.x + threadIdx.x;
    if (idx >= N_NODES*576) return;
    int n = idx/576, j = idx%576;
    float v;
    if (j < 64)       v =        g_feat[n*FSTRIDE + j];
    else if (j < 256){ int jj=j-64;  v = 0.5f  * g_feat[n*FSTRIDE + (1+jj%3)*64 + jj/3]; }
    else             { int jj=j-256; v = 0.25f * g_feat[n*FSTRIDE + (4+jj%5)*64 + jj/5]; }
    out[idx] = v;
}

// ---------------- launch ----------------
extern "C" void kernel_launch(void* const* d_in, const int* in_sizes, int n_in,
                              void* d_out, int out_size){
    const float* positions = (const float*)d_in[0];
    const int*   species   = (const int*)  d_in[1];
    const int*   senders   = (const int*)  d_in[2];
    const int*   receivers = (const int*)  d_in[3];
    const float* embed     = (const float*)d_in[4];
    const float* w_proj    = (const float*)d_in[5];
    const float* mlp_w1    = (const float*)d_in[6];
    const float* mlp_b1    = (const float*)d_in[7];
    const float* mlp_w2    = (const float*)d_in[8];
    const float* mlp_b2    = (const float*)d_in[9];
    const float* mlp_w3    = (const float*)d_in[10];
    const float* lin_self  = (const float*)d_in[11];
    const float* gate_w    = (const float*)d_in[12];
    const float* gate_b    = (const float*)d_in[13];
    float* out = (float*)d_out;

    cudaFuncSetAttribute(wgemm_fused, cudaFuncAttributeMaxDynamicSharedMemorySize, WG_SMEM);

    cg_zero_kernel<<<NPATHS + N_NODES/128, 128>>>();             // launch 0
    csr_count<<<N_EDGES/256, 256>>>(receivers);                  // launch 1
    csr_scan<<<1, 256>>>();                                      // launch 2
    csr_scatter<<<N_EDGES/256, 256>>>(senders, receivers);       // launch 3 (profiled)
    geo_init_kernel<<<GEO_BLOCKS + INIT_BLOCKS, 256>>>(          // launch 4
        positions, species, embed, w_proj);

    for (int L=0; L<2; L++){
        wgemm_fused<<<N_EDGES/128, 256, WG_SMEM>>>(              // launch 5, 7
            mlp_w1 + L*8*64,  mlp_b1 + L*64,
            mlp_w2 + L*64*64, mlp_b2 + L*64,
            mlp_w3 + L*64*960);
        node_fused<<<N_NODES, 256>>>(lin_self, gate_w, gate_b, L);  // launch 6, 8
    }
    out_kernel<<<(N_NODES*576)/256, 256>>>(out);                 // launch 9
}